// round 6
// baseline (speedup 1.0000x reference)
#include <cuda_runtime.h>
#include <cuda_fp16.h>
#include <cstdint>

#define EPSILON_F 1e-9f
#define NQ 100
#define L_SEQ 512

// Persistent: 1 CTA/SM, fp16 table in smem.
// Depth-2 software pipeline (ping-pong buffers) so each SM keeps ~32KB of
// index loads in flight (latency-BW product for ~7TB/s). Scalar part
// (trapz + scattering) computed per-block during table staging.
__global__ __launch_bounds__(1024, 1)
void gather_kernel(const int* __restrict__ idx,
                   const float* __restrict__ eta,
                   const float* __restrict__ t_ptr,
                   float* __restrict__ out, int B, int V) {
    extern __shared__ __half sh[];
    // small scratch after the table (aligned)
    float* ws = reinterpret_cast<float*>(sh + ((V + 7) & ~7));

    const int tid   = threadIdx.x;
    const int warp  = tid >> 5;
    const int lane  = tid & 31;
    const int warps = blockDim.x >> 5;            // 32
    const int stride = gridDim.x * warps;

    const float t = __ldg(t_ptr);

    // ---- issue first two rows' index loads EARLY (hidden by staging) ----
    const int row0 = blockIdx.x * warps + warp;
    const int row1 = row0 + stride;
    int4 buf0[4], buf1[4];
    if (row0 < B) {
        const int4* p = reinterpret_cast<const int4*>(idx + (size_t)row0 * L_SEQ);
        #pragma unroll
        for (int j = 0; j < 4; j++) buf0[j] = __ldcs(&p[j * 32 + lane]);
    }
    if (row1 < B) {
        const int4* p = reinterpret_cast<const int4*>(idx + (size_t)row1 * L_SEQ);
        #pragma unroll
        for (int j = 0; j < 4; j++) buf1[j] = __ldcs(&p[j * 32 + lane]);
    }

    // ---- scalar part: trapz(exp(-E),E) over 100 pts, warps 0-3 ----
    if (tid < 128) {
        float val = 0.0f;
        if (tid < NQ - 1) {
            float Ei = ((float)tid       * (1.0f / (NQ - 1))) * t;
            float Ej = ((float)(tid + 1) * (1.0f / (NQ - 1))) * t;
            val = 0.5f * (__expf(-Ei) + __expf(-Ej)) * (Ej - Ei);
        }
        #pragma unroll
        for (int off = 16; off; off >>= 1)
            val += __shfl_xor_sync(0xffffffffu, val, off);
        if (lane == 0) ws[warp] = val;
    }

    // ---- stage table: fp32 -> fp16 smem (vectorized) ----
    const int nv4 = V >> 2;
    const float4* e4 = reinterpret_cast<const float4*>(eta);
    for (int i = tid; i < nv4; i += blockDim.x) {
        float4 v = __ldg(e4 + i);
        __half2* dst = reinterpret_cast<__half2*>(sh + 4 * i);
        dst[0] = __floats2half2_rn(v.x, v.y);
        dst[1] = __floats2half2_rn(v.z, v.w);
    }
    for (int i = (nv4 << 2) + tid; i < V; i += blockDim.x)
        sh[i] = __float2half_rn(__ldg(eta + i));
    __syncthreads();

    const float base = (ws[0] + ws[1] + ws[2] + ws[3])
                     - 0.5f * t * logf(t + EPSILON_F);

    // ---- main loop: 2-unrolled ping-pong, prefetch distance 2 ----
    int row = row0;
    while (row < B) {
        // half A: consume buf0, prefetch buf0 <- row + 2*stride
        {
            const int pre = row + 2 * stride;
            int4 nxt[4];
            if (pre < B) {
                const int4* p = reinterpret_cast<const int4*>(idx + (size_t)pre * L_SEQ);
                #pragma unroll
                for (int j = 0; j < 4; j++) nxt[j] = __ldcs(&p[j * 32 + lane]);
            }
            float a = 0.0f, b = 0.0f;
            #pragma unroll
            for (int j = 0; j < 4; j++) {
                a += __half2float(sh[buf0[j].x]);
                b += __half2float(sh[buf0[j].y]);
                a += __half2float(sh[buf0[j].z]);
                b += __half2float(sh[buf0[j].w]);
            }
            float s = a + b;
            #pragma unroll
            for (int off = 16; off; off >>= 1)
                s += __shfl_xor_sync(0xffffffffu, s, off);
            if (lane == 0) out[row] = s + base;
            #pragma unroll
            for (int j = 0; j < 4; j++) buf0[j] = nxt[j];
        }
        row += stride;
        if (row >= B) break;

        // half B: consume buf1, prefetch buf1 <- row + 2*stride
        {
            const int pre = row + 2 * stride;
            int4 nxt[4];
            if (pre < B) {
                const int4* p = reinterpret_cast<const int4*>(idx + (size_t)pre * L_SEQ);
                #pragma unroll
                for (int j = 0; j < 4; j++) nxt[j] = __ldcs(&p[j * 32 + lane]);
            }
            float a = 0.0f, b = 0.0f;
            #pragma unroll
            for (int j = 0; j < 4; j++) {
                a += __half2float(sh[buf1[j].x]);
                b += __half2float(sh[buf1[j].y]);
                a += __half2float(sh[buf1[j].z]);
                b += __half2float(sh[buf1[j].w]);
            }
            float s = a + b;
            #pragma unroll
            for (int off = 16; off; off >>= 1)
                s += __shfl_xor_sync(0xffffffffu, s, off);
            if (lane == 0) out[row] = s + base;
            #pragma unroll
            for (int j = 0; j < 4; j++) buf1[j] = nxt[j];
        }
        row += stride;
    }
}

extern "C" void kernel_launch(void* const* d_in, const int* in_sizes, int n_in,
                              void* d_out, int out_size) {
    const int*   idx = (const int*)d_in[0];     // [B, 512] int32
    const float* eta = (const float*)d_in[1];   // [V] f32
    const float* t   = (const float*)d_in[2];   // scalar f32
    float* out = (float*)d_out;

    const int B = in_sizes[0] / L_SEQ;
    const int V = in_sizes[1];

    int dev = 0, sms = 148;
    cudaGetDevice(&dev);
    cudaDeviceGetAttribute(&sms, cudaDevAttrMultiProcessorCount, dev);

    size_t smem = (size_t)((V + 7) & ~7) * sizeof(__half) + 64 * sizeof(float);
    cudaFuncSetAttribute(gather_kernel,
                         cudaFuncAttributeMaxDynamicSharedMemorySize, (int)smem);

    gather_kernel<<<sms, 1024, smem>>>(idx, eta, t, out, B, V);
}

// round 7
// speedup vs baseline: 1.0601x; 1.0601x over previous
#include <cuda_runtime.h>
#include <cuda_fp16.h>
#include <cstdint>

#define EPSILON_F 1e-9f
#define NQ 100
#define L_SEQ 512

// Persistent: 1 CTA/SM (smem-bound), 512 threads so the reg ceiling is 128.
// fp16 table in smem; depth-4 register ring of index buffers keeps
// 16 warps x 4 rows x 512B = 32KB/SM of LDG in flight -> DRAM-bound.
__global__ __launch_bounds__(512, 1)
void gather_kernel(const int* __restrict__ idx,
                   const float* __restrict__ eta,
                   const float* __restrict__ t_ptr,
                   float* __restrict__ out, int B, int V) {
    extern __shared__ __half sh[];
    float* ws = reinterpret_cast<float*>(sh + ((V + 7) & ~7));

    const int tid    = threadIdx.x;
    const int warp   = tid >> 5;
    const int lane   = tid & 31;
    const int warps  = blockDim.x >> 5;           // 16
    const int stride = gridDim.x * warps;

    const float t = __ldg(t_ptr);

    // ---- prologue: issue 4 rows' index loads EARLY (hidden by staging) ----
    const int row0 = blockIdx.x * warps + warp;
    int4 buf0[4], buf1[4], buf2[4], buf3[4];
    {
        const int r1 = row0 + stride, r2 = row0 + 2 * stride, r3 = row0 + 3 * stride;
        if (row0 < B) {
            const int4* p = reinterpret_cast<const int4*>(idx + (size_t)row0 * L_SEQ);
            #pragma unroll
            for (int j = 0; j < 4; j++) buf0[j] = __ldcs(&p[j * 32 + lane]);
        }
        if (r1 < B) {
            const int4* p = reinterpret_cast<const int4*>(idx + (size_t)r1 * L_SEQ);
            #pragma unroll
            for (int j = 0; j < 4; j++) buf1[j] = __ldcs(&p[j * 32 + lane]);
        }
        if (r2 < B) {
            const int4* p = reinterpret_cast<const int4*>(idx + (size_t)r2 * L_SEQ);
            #pragma unroll
            for (int j = 0; j < 4; j++) buf2[j] = __ldcs(&p[j * 32 + lane]);
        }
        if (r3 < B) {
            const int4* p = reinterpret_cast<const int4*>(idx + (size_t)r3 * L_SEQ);
            #pragma unroll
            for (int j = 0; j < 4; j++) buf3[j] = __ldcs(&p[j * 32 + lane]);
        }
    }

    // ---- scalar part: trapz(exp(-E),E), warps 0-3 ----
    if (tid < 128) {
        float val = 0.0f;
        if (tid < NQ - 1) {
            float Ei = ((float)tid       * (1.0f / (NQ - 1))) * t;
            float Ej = ((float)(tid + 1) * (1.0f / (NQ - 1))) * t;
            val = 0.5f * (__expf(-Ei) + __expf(-Ej)) * (Ej - Ei);
        }
        #pragma unroll
        for (int off = 16; off; off >>= 1)
            val += __shfl_xor_sync(0xffffffffu, val, off);
        if (lane == 0) ws[warp] = val;
    }

    // ---- stage table fp32 -> fp16 smem, unrolled x4 for L2-latency MLP ----
    {
        const int nv4 = V >> 2;
        const float4* e4 = reinterpret_cast<const float4*>(eta);
        int i = tid;
        for (; i + 3 * (int)blockDim.x < nv4; i += 4 * blockDim.x) {
            float4 v0 = __ldg(e4 + i);
            float4 v1 = __ldg(e4 + i + blockDim.x);
            float4 v2 = __ldg(e4 + i + 2 * blockDim.x);
            float4 v3 = __ldg(e4 + i + 3 * blockDim.x);
            __half2* d0 = reinterpret_cast<__half2*>(sh + 4 * i);
            __half2* d1 = reinterpret_cast<__half2*>(sh + 4 * (i + blockDim.x));
            __half2* d2 = reinterpret_cast<__half2*>(sh + 4 * (i + 2 * blockDim.x));
            __half2* d3 = reinterpret_cast<__half2*>(sh + 4 * (i + 3 * blockDim.x));
            d0[0] = __floats2half2_rn(v0.x, v0.y); d0[1] = __floats2half2_rn(v0.z, v0.w);
            d1[0] = __floats2half2_rn(v1.x, v1.y); d1[1] = __floats2half2_rn(v1.z, v1.w);
            d2[0] = __floats2half2_rn(v2.x, v2.y); d2[1] = __floats2half2_rn(v2.z, v2.w);
            d3[0] = __floats2half2_rn(v3.x, v3.y); d3[1] = __floats2half2_rn(v3.z, v3.w);
        }
        for (; i < nv4; i += blockDim.x) {
            float4 v = __ldg(e4 + i);
            __half2* dst = reinterpret_cast<__half2*>(sh + 4 * i);
            dst[0] = __floats2half2_rn(v.x, v.y);
            dst[1] = __floats2half2_rn(v.z, v.w);
        }
        for (int k = (nv4 << 2) + tid; k < V; k += blockDim.x)
            sh[k] = __float2half_rn(__ldg(eta + k));
    }
    __syncthreads();

    const float base = (ws[0] + ws[1] + ws[2] + ws[3])
                     - 0.5f * t * logf(t + EPSILON_F);

    if (row0 >= B) return;
    int row = row0;

    // one pipeline stage: gather BUF's row, refill BUF from row+4*stride
    #define STAGE(BUF)                                                        \
    {                                                                         \
        float a = 0.0f, b = 0.0f;                                             \
        _Pragma("unroll")                                                     \
        for (int j = 0; j < 4; j++) {                                         \
            a += __half2float(sh[BUF[j].x]);                                  \
            b += __half2float(sh[BUF[j].y]);                                  \
            a += __half2float(sh[BUF[j].z]);                                  \
            b += __half2float(sh[BUF[j].w]);                                  \
        }                                                                     \
        const int pre = row + 4 * stride;                                     \
        if (pre < B) {                                                        \
            const int4* p = reinterpret_cast<const int4*>(                    \
                idx + (size_t)pre * L_SEQ);                                   \
            _Pragma("unroll")                                                 \
            for (int j = 0; j < 4; j++) BUF[j] = __ldcs(&p[j * 32 + lane]);   \
        }                                                                     \
        float s = a + b;                                                      \
        _Pragma("unroll")                                                     \
        for (int off = 16; off; off >>= 1)                                    \
            s += __shfl_xor_sync(0xffffffffu, s, off);                        \
        if (lane == 0) out[row] = s + base;                                   \
    }

    for (;;) {
        STAGE(buf0); row += stride; if (row >= B) break;
        STAGE(buf1); row += stride; if (row >= B) break;
        STAGE(buf2); row += stride; if (row >= B) break;
        STAGE(buf3); row += stride; if (row >= B) break;
    }
    #undef STAGE
}

extern "C" void kernel_launch(void* const* d_in, const int* in_sizes, int n_in,
                              void* d_out, int out_size) {
    const int*   idx = (const int*)d_in[0];     // [B, 512] int32
    const float* eta = (const float*)d_in[1];   // [V] f32
    const float* t   = (const float*)d_in[2];   // scalar f32
    float* out = (float*)d_out;

    const int B = in_sizes[0] / L_SEQ;
    const int V = in_sizes[1];

    int dev = 0, sms = 148;
    cudaGetDevice(&dev);
    cudaDeviceGetAttribute(&sms, cudaDevAttrMultiProcessorCount, dev);

    size_t smem = (size_t)((V + 7) & ~7) * sizeof(__half) + 64 * sizeof(float);
    cudaFuncSetAttribute(gather_kernel,
                         cudaFuncAttributeMaxDynamicSharedMemorySize, (int)smem);

    gather_kernel<<<sms, 512, smem>>>(idx, eta, t, out, B, V);
}